// round 5
// baseline (speedup 1.0000x reference)
#include <cuda_runtime.h>
#include <cstdint>
#include <cstddef>

#define BB   2
#define LLEN 1024
#define CAx  512
#define CSx  384
#define CZx  64
#define HHx  16
#define DDx  32
#define MR   (BB*LLEN)
#define TQ   8
#define TK   8
#define SCALE_QK 0.17677669529663687f  // 1/sqrt(32)

typedef unsigned long long ull;
#define DINL __device__ __forceinline__

// ---------------- f32x2 packed helpers (full fp32 precision, 2x FMA rate) ----
DINL ull pk2(float x, float y){
    ull r; asm("mov.b64 %0, {%1,%2};" : "=l"(r) : "r"(__float_as_uint(x)), "r"(__float_as_uint(y)));
    return r;
}
DINL ull dup2(float x){
    unsigned u = __float_as_uint(x); ull r;
    asm("mov.b64 %0, {%1,%1};" : "=l"(r) : "r"(u));
    return r;
}
DINL float2 upk2(ull v){
    unsigned a, b; asm("mov.b64 {%0,%1}, %2;" : "=r"(a), "=r"(b) : "l"(v));
    return make_float2(__uint_as_float(a), __uint_as_float(b));
}
DINL ull ffma2(ull a, ull b, ull c){
    ull d; asm("fma.rn.f32x2 %0, %1, %2, %3;" : "=l"(d) : "l"(a), "l"(b), "l"(c));
    return d;
}
DINL ull fmul2(ull a, ull b){
    ull d; asm("mul.rn.f32x2 %0, %1, %2;" : "=l"(d) : "l"(a), "l"(b));
    return d;
}
DINL float sigf(float x){ return 1.0f / (1.0f + __expf(-x)); }

// ---------------- scratch (device globals: allocation-free) ------------------
__device__ float g_sln  [MR*CSx];
__device__ float g_aln  [MR*CAx];
__device__ float g_P1   [MR*CAx];
__device__ float g_anorm[MR*CAx];
__device__ float g_Q    [MR*CAx];
__device__ float g_K    [MR*CAx];
__device__ float g_V    [MR*CAx];
__device__ float g_G    [MR*CAx];
__device__ float g_GL   [MR*CAx];
__device__ float g_O    [MR*CAx];
__device__ float g_maskf[MR];
__device__ int   g_masktype;

// ---------------- mask dtype sniffing + canonical decode ---------------------
// The reference mask is a numpy bool array; the harness may deliver it as
// bool/u8, int32, int64, or float32. Detect from the first 2048 bytes (always
// in-bounds for 2048 elements of any of those dtypes), then decode to float.
__global__ void mask_detect_kernel(const unsigned char* __restrict__ m)
{
    __shared__ int s_na;    // all bytes at idx%4!=0 are zero   -> int32/int64
    __shared__ int s_odd0;  // all odd int32 words are zero     -> int64
    __shared__ int s_f32;   // floats all in {0,1}              -> float32
    int tid = threadIdx.x;
    if (tid == 0){ s_na = 1; s_odd0 = 1; s_f32 = 1; }
    __syncthreads();
    for (int i = tid; i < 2048; i += 256){
        if ((i & 3) != 0 && m[i] != 0) atomicAnd(&s_na, 0);
    }
    const unsigned* mu = (const unsigned*)m;
    for (int i = tid; i < 512; i += 256){
        if ((i & 1) != 0 && mu[i] != 0u) atomicAnd(&s_odd0, 0);
        float f = __uint_as_float(mu[i]);
        if (!(f == 0.0f || f == 1.0f)) atomicAnd(&s_f32, 0);
    }
    __syncthreads();
    if (tid == 0){
        int t;
        if (s_na)       t = s_odd0 ? 3 : 1;   // 3 = int64, 1 = int32
        else if (s_f32) t = 2;                // 2 = float32
        else            t = 0;                // 0 = bool/u8
        g_masktype = t;
    }
}

__global__ void mask_expand_kernel(const void* __restrict__ m)
{
    int i = blockIdx.x * 256 + threadIdx.x;
    if (i >= MR) return;
    int t = g_masktype;
    float v;
    if (t == 0)      v = ((const unsigned char*)m)[i] ? 1.f : 0.f;
    else if (t == 1) v = ((const int*)m)[i] ? 1.f : 0.f;
    else if (t == 2) v = (((const float*)m)[i] != 0.f) ? 1.f : 0.f;
    else             v = ((const long long*)m)[i] ? 1.f : 0.f;
    g_maskf[i] = v;
}

// ---------------- LayerNorm kernel: rows of a (512) and s (384) --------------
__global__ void __launch_bounds__(128) ln_kernel(
    const float* __restrict__ a, const float* __restrict__ s,
    const float* __restrict__ lnss,
    float* __restrict__ aln, float* __restrict__ sln)
{
    __shared__ float redA[8], redB[8];
    int r = blockIdx.x, tid = threadIdx.x;
    int lane = tid & 31, wid = tid >> 5;

    const float* ar = a + (size_t)r * CAx;
    float4 av = *(const float4*)(ar + tid * 4);
    float s1 = av.x + av.y + av.z + av.w;
    float s2 = av.x*av.x + av.y*av.y + av.z*av.z + av.w*av.w;
    #pragma unroll
    for (int o = 16; o > 0; o >>= 1){
        s1 += __shfl_xor_sync(~0u, s1, o);
        s2 += __shfl_xor_sync(~0u, s2, o);
    }
    if (lane == 0){ redA[wid] = s1; redA[4+wid] = s2; }

    float4 sv = make_float4(0.f,0.f,0.f,0.f);
    if (tid < 96) sv = *(const float4*)(s + (size_t)r * CSx + tid * 4);
    float t1 = sv.x + sv.y + sv.z + sv.w;
    float t2 = sv.x*sv.x + sv.y*sv.y + sv.z*sv.z + sv.w*sv.w;
    #pragma unroll
    for (int o = 16; o > 0; o >>= 1){
        t1 += __shfl_xor_sync(~0u, t1, o);
        t2 += __shfl_xor_sync(~0u, t2, o);
    }
    if (lane == 0){ redB[wid] = t1; redB[4+wid] = t2; }
    __syncthreads();

    float as1 = redA[0]+redA[1]+redA[2]+redA[3];
    float as2 = redA[4]+redA[5]+redA[6]+redA[7];
    float am = as1 * (1.f/CAx);
    float arstd = rsqrtf(as2*(1.f/CAx) - am*am + 1e-5f);
    float4 ao;
    ao.x = (av.x-am)*arstd; ao.y = (av.y-am)*arstd;
    ao.z = (av.z-am)*arstd; ao.w = (av.w-am)*arstd;
    *(float4*)(aln + (size_t)r*CAx + tid*4) = ao;

    float bs1 = redB[0]+redB[1]+redB[2]+redB[3];
    float bs2 = redB[4]+redB[5]+redB[6]+redB[7];
    float sm = bs1 * (1.f/CSx);
    float srstd = rsqrtf(bs2*(1.f/CSx) - sm*sm + 1e-5f);
    if (tid < 96){
        float4 sc = *(const float4*)(lnss + tid*4);
        float4 so;
        so.x = (sv.x-sm)*srstd*sc.x; so.y = (sv.y-sm)*srstd*sc.y;
        so.z = (sv.z-sm)*srstd*sc.z; so.w = (sv.w-sm)*srstd*sc.w;
        *(float4*)(sln + (size_t)r*CSx + tid*4) = so;
    }
}

// ---------------- tiled fp32 GEMM: C[M,N] = A[M,K] @ W[N,K]^T (+epilogue) ----
// MODE 0: C = acc + bias
// MODE 1: C = sigmoid(acc + bias)
// MODE 2: C = (acc + bias) * aux1[m,n] * maskf[m]
// MODE 3: C = aux1[m,n] * aux2[m,n] + acc
template<int MODE>
__global__ void __launch_bounds__(128) gemm_kernel(
    const float* __restrict__ A, int lda,
    const float* __restrict__ W, int K,
    const float* __restrict__ bias,
    const float* __restrict__ aux1, const float* __restrict__ aux2,
    const float* __restrict__ maskf,
    float* __restrict__ C, int N)
{
    __shared__ float As[16][68];   // [k][m]
    __shared__ float Bs[16][68];   // [k][n]
    int tid = threadIdx.x;
    int tn = tid & 15, tm = tid >> 4;
    int m0 = blockIdx.y * 64, n0 = blockIdx.x * 64;

    ull acc[4][4];
    #pragma unroll
    for (int i=0;i<4;i++)
        #pragma unroll
        for (int j=0;j<4;j++) acc[i][j] = 0ull;

    for (int k0 = 0; k0 < K; k0 += 16){
        __syncthreads();
        #pragma unroll
        for (int i=0;i<2;i++){
            int u = tid + i*128;
            int m = u >> 2, kc = (u & 3) << 2;
            float4 v = *(const float4*)(A + (size_t)(m0+m)*lda + k0 + kc);
            As[kc+0][m]=v.x; As[kc+1][m]=v.y; As[kc+2][m]=v.z; As[kc+3][m]=v.w;
        }
        #pragma unroll
        for (int i=0;i<2;i++){
            int u = tid + i*128;
            int n = u >> 2, kc = (u & 3) << 2;
            float4 v = *(const float4*)(W + (size_t)(n0+n)*K + k0 + kc);
            Bs[kc+0][n]=v.x; Bs[kc+1][n]=v.y; Bs[kc+2][n]=v.z; Bs[kc+3][n]=v.w;
        }
        __syncthreads();
        #pragma unroll
        for (int kk=0; kk<16; kk++){
            ulonglong2 a01 = *(const ulonglong2*)(&As[kk][tm*8]);
            ulonglong2 a23 = *(const ulonglong2*)(&As[kk][tm*8+4]);
            float4 b4 = *(const float4*)(&Bs[kk][tn*4]);
            ull b0 = dup2(b4.x), b1 = dup2(b4.y), b2 = dup2(b4.z), b3 = dup2(b4.w);
            ull am[4] = {a01.x, a01.y, a23.x, a23.y};
            #pragma unroll
            for (int j=0;j<4;j++){
                acc[j][0] = ffma2(am[j], b0, acc[j][0]);
                acc[j][1] = ffma2(am[j], b1, acc[j][1]);
                acc[j][2] = ffma2(am[j], b2, acc[j][2]);
                acc[j][3] = ffma2(am[j], b3, acc[j][3]);
            }
        }
    }

    float4 bv = make_float4(0.f,0.f,0.f,0.f);
    if ((MODE == 0 || MODE == 1 || MODE == 2) && bias)
        bv = *(const float4*)(bias + n0 + tn*4);

    #pragma unroll
    for (int j=0;j<4;j++){
        int row0 = m0 + tm*8 + 2*j;
        int row1 = row0 + 1;
        float2 c0 = upk2(acc[j][0]), c1 = upk2(acc[j][1]);
        float2 c2 = upk2(acc[j][2]), c3 = upk2(acc[j][3]);
        float4 r0 = make_float4(c0.x, c1.x, c2.x, c3.x);
        float4 r1 = make_float4(c0.y, c1.y, c2.y, c3.y);
        int col = n0 + tn*4;
        if (MODE == 0 || MODE == 1 || MODE == 2){
            r0.x += bv.x; r0.y += bv.y; r0.z += bv.z; r0.w += bv.w;
            r1.x += bv.x; r1.y += bv.y; r1.z += bv.z; r1.w += bv.w;
        }
        if (MODE == 1){
            r0.x = sigf(r0.x); r0.y = sigf(r0.y); r0.z = sigf(r0.z); r0.w = sigf(r0.w);
            r1.x = sigf(r1.x); r1.y = sigf(r1.y); r1.z = sigf(r1.z); r1.w = sigf(r1.w);
        }
        if (MODE == 2){
            float4 g0 = *(const float4*)(aux1 + (size_t)row0*N + col);
            float4 g1 = *(const float4*)(aux1 + (size_t)row1*N + col);
            float mk0 = maskf[row0];
            float mk1 = maskf[row1];
            r0.x *= g0.x*mk0; r0.y *= g0.y*mk0; r0.z *= g0.z*mk0; r0.w *= g0.w*mk0;
            r1.x *= g1.x*mk1; r1.y *= g1.y*mk1; r1.z *= g1.z*mk1; r1.w *= g1.w*mk1;
        }
        if (MODE == 3){
            float4 p0 = *(const float4*)(aux1 + (size_t)row0*N + col);
            float4 p1 = *(const float4*)(aux1 + (size_t)row1*N + col);
            float4 l0 = *(const float4*)(aux2 + (size_t)row0*N + col);
            float4 l1 = *(const float4*)(aux2 + (size_t)row1*N + col);
            r0.x += p0.x*l0.x; r0.y += p0.y*l0.y; r0.z += p0.z*l0.z; r0.w += p0.w*l0.w;
            r1.x += p1.x*l1.x; r1.y += p1.y*l1.y; r1.z += p1.z*l1.z; r1.w += p1.w*l1.w;
        }
        *(float4*)(C + (size_t)row0*N + col) = r0;
        *(float4*)(C + (size_t)row1*N + col) = r1;
    }
}

// ---------------- fused flash attention with pair bias from z ----------------
#define ZS_N   (64*68)
#define KS_N   (16*260)
#define US_N   (16*68)
#define SMEMB  ((ZS_N + 2*KS_N + US_N + 16 + 64 + 64 + 8) * 4)

__global__ void __launch_bounds__(128, 4) attn_kernel(
    const float* __restrict__ Qg, const float* __restrict__ Kg,
    const float* __restrict__ Vg, const float* __restrict__ Gg,
    const float* __restrict__ z,  const float* __restrict__ lnz,
    const float* __restrict__ wz, const float* __restrict__ maskf,
    float* __restrict__ O)
{
    extern __shared__ float smf[];
    float* zs    = smf;
    float* Ks    = zs + ZS_N;
    float* Vs    = Ks + KS_N;
    float* us    = Vs + KS_N;
    float* usums = us + US_N;
    float* means = usums + 16;
    float* rstds = means + 64;
    float* maskk = rstds + 64;

    int tid = threadIdx.x;
    int h = tid & 15, qi = tid >> 4;
    int b = blockIdx.y;
    int q0 = blockIdx.x * TQ;
    int rowq = b*LLEN + q0 + qi;

    // stage u[h][c] = lnz_scale[c] * wz[h][c]
    for (int i = tid; i < 16*64; i += 128){
        int hh = i >> 6, c = i & 63;
        us[hh*68 + c] = lnz[c] * wz[hh*64 + c];
    }
    __syncthreads();
    if (tid < 16){
        float ssum = 0.f;
        #pragma unroll
        for (int c=0;c<64;c++) ssum += us[tid*68 + c];
        usums[tid] = ssum;
    }

    ull q2[16];
    {
        const float* qp = Qg + (size_t)rowq*CAx + h*DDx;
        #pragma unroll
        for (int d4=0; d4<8; d4++){
            float4 v = *(const float4*)(qp + d4*4);
            q2[2*d4]   = pk2(v.x*SCALE_QK, v.y*SCALE_QK);
            q2[2*d4+1] = pk2(v.z*SCALE_QK, v.w*SCALE_QK);
        }
    }
    float mq = maskf[rowq];

    ull o2[16];
    #pragma unroll
    for (int i=0;i<16;i++) o2[i] = 0ull;
    float mrun = -1e30f, denom = 0.f;

    for (int kt = 0; kt < LLEN/TK; kt++){
        int k0 = kt * TK;
        __syncthreads();
        #pragma unroll
        for (int i=0;i<8;i++){
            int u = tid + i*128;
            int qq = u >> 7;
            int rem = u & 127;
            int kk = rem >> 4, c4 = rem & 15;
            float4 v = *(const float4*)(z + ((size_t)((b*LLEN + q0 + qq))*LLEN + k0 + kk)*CZx + c4*4);
            *(float4*)(zs + (kk*8 + qq)*68 + c4*4) = v;
        }
        #pragma unroll
        for (int i=0;i<8;i++){
            int u = tid + i*128;
            int kk = u >> 7;
            int c4 = u & 127;
            int hh = c4 >> 3, d4 = c4 & 7;
            size_t gro = ((size_t)(b*LLEN + k0 + kk))*CAx + c4*4;
            float4 kv = *(const float4*)(Kg + gro);
            *(float4*)(Ks + hh*260 + kk*32 + d4*4) = kv;
            float4 vv = *(const float4*)(Vg + gro);
            *(float4*)(Vs + hh*260 + kk*32 + d4*4) = vv;
        }
        if (tid < TK) maskk[tid] = maskf[b*LLEN + k0 + tid];
        __syncthreads();
        {
            int tp = tid & 1, p = tid >> 1;
            const float* zr = zs + p*68 + tp*32;
            float s1 = 0.f, s2 = 0.f;
            #pragma unroll
            for (int c=0;c<32;c+=4){
                float4 v = *(const float4*)(zr + c);
                s1 += v.x+v.y+v.z+v.w;
                s2 += v.x*v.x + v.y*v.y + v.z*v.z + v.w*v.w;
            }
            s1 += __shfl_xor_sync(~0u, s1, 1);
            s2 += __shfl_xor_sync(~0u, s2, 1);
            if (tp == 0){
                float mean = s1 * (1.f/64);
                float var  = s2 * (1.f/64) - mean*mean;
                means[p] = mean;
                rstds[p] = rsqrtf(var + 1e-5f);
            }
        }
        __syncthreads();
        for (int kk=0; kk<TK; kk++){
            if (maskk[kk] == 0.f) continue;   // uniform branch
            const float* zr = zs + (kk*8 + qi)*68;
            const float* ur = us + h*68;
            ull bd = 0ull;
            #pragma unroll
            for (int c4=0; c4<16; c4++){
                ulonglong2 zz = *(const ulonglong2*)(zr + c4*4);
                ulonglong2 uu = *(const ulonglong2*)(ur + c4*4);
                bd = ffma2(zz.x, uu.x, bd);
                bd = ffma2(zz.y, uu.y, bd);
            }
            float2 bf = upk2(bd);
            int p = kk*8 + qi;
            float bias = rstds[p] * ((bf.x + bf.y) - means[p]*usums[h]);

            const float* kr = Ks + h*260 + kk*32;
            ull qa = 0ull;
            #pragma unroll
            for (int d4=0; d4<8; d4++){
                ulonglong2 kk2 = *(const ulonglong2*)(kr + d4*4);
                qa = ffma2(kk2.x, q2[2*d4],   qa);
                qa = ffma2(kk2.y, q2[2*d4+1], qa);
            }
            float2 qf = upk2(qa);
            float l = qf.x + qf.y + bias;

            const float* vr = Vs + h*260 + kk*32;
            if (l > mrun){
                float corr = __expf(mrun - l);
                mrun = l;
                denom = denom*corr + 1.f;
                ull c2 = dup2(corr);
                #pragma unroll
                for (int d4=0; d4<8; d4++){
                    ulonglong2 vv = *(const ulonglong2*)(vr + d4*4);
                    o2[2*d4]   = ffma2(o2[2*d4],   c2, vv.x);
                    o2[2*d4+1] = ffma2(o2[2*d4+1], c2, vv.y);
                }
            } else {
                float pe = __expf(l - mrun);
                denom += pe;
                ull p2v = dup2(pe);
                #pragma unroll
                for (int d4=0; d4<8; d4++){
                    ulonglong2 vv = *(const ulonglong2*)(vr + d4*4);
                    o2[2*d4]   = ffma2(vv.x, p2v, o2[2*d4]);
                    o2[2*d4+1] = ffma2(vv.y, p2v, o2[2*d4+1]);
                }
            }
        }
    }

    float inv = (denom > 0.f) ? (mq / denom) : 0.f;
    ull inv2 = dup2(inv);
    const float* gp = Gg + (size_t)rowq*CAx + h*DDx;
    float* op = O + (size_t)rowq*CAx + h*DDx;
    #pragma unroll
    for (int d4=0; d4<8; d4++){
        float4 g4 = *(const float4*)(gp + d4*4);
        float2 aa = upk2(fmul2(o2[2*d4],   inv2));
        float2 bb = upk2(fmul2(o2[2*d4+1], inv2));
        float4 r = make_float4(aa.x*g4.x, aa.y*g4.y, bb.x*g4.z, bb.y*g4.w);
        *(float4*)(op + d4*4) = r;
    }
}

// ---------------- launch ----------------------------------------------------
extern "C" void kernel_launch(void* const* d_in, const int* in_sizes, int n_in,
                              void* d_out, int out_size)
{
    const float* a      = (const float*)d_in[0];
    const float* s      = (const float*)d_in[1];
    const float* z      = (const float*)d_in[2];
    const float* lnss   = (const float*)d_in[3];
    const float* ada_ws = (const float*)d_in[4];
    const float* ada_bs = (const float*)d_in[5];
    const float* ada_nb = (const float*)d_in[6];
    const float* wq     = (const float*)d_in[7];
    const float* bq     = (const float*)d_in[8];
    const float* wk     = (const float*)d_in[9];
    const float* bk     = (const float*)d_in[10];
    const float* wv     = (const float*)d_in[11];
    const float* bv     = (const float*)d_in[12];
    const float* wg     = (const float*)d_in[13];
    const float* bg     = (const float*)d_in[14];
    const float* wo     = (const float*)d_in[15];
    const float* bo     = (const float*)d_in[16];
    const float* lnz    = (const float*)d_in[17];
    const float* wz     = (const float*)d_in[18];
    const float* wl     = (const float*)d_in[19];
    const float* bl     = (const float*)d_in[20];
    const void*  maskraw= d_in[21];
    float* out = (float*)d_out;

    float *p_sln, *p_aln, *p_P1, *p_anorm, *p_Q, *p_K, *p_V, *p_G, *p_GL, *p_O, *p_mf;
    cudaGetSymbolAddress((void**)&p_sln,   g_sln);
    cudaGetSymbolAddress((void**)&p_aln,   g_aln);
    cudaGetSymbolAddress((void**)&p_P1,    g_P1);
    cudaGetSymbolAddress((void**)&p_anorm, g_anorm);
    cudaGetSymbolAddress((void**)&p_Q,     g_Q);
    cudaGetSymbolAddress((void**)&p_K,     g_K);
    cudaGetSymbolAddress((void**)&p_V,     g_V);
    cudaGetSymbolAddress((void**)&p_G,     g_G);
    cudaGetSymbolAddress((void**)&p_GL,    g_GL);
    cudaGetSymbolAddress((void**)&p_O,     g_O);
    cudaGetSymbolAddress((void**)&p_mf,    g_maskf);

    cudaFuncSetAttribute(attn_kernel, cudaFuncAttributeMaxDynamicSharedMemorySize, SMEMB);

    dim3 gN8(CAx/64, MR/64);   // (8, 32)

    // 0. canonicalize mask -> float[MR]
    mask_detect_kernel<<<1, 256>>>((const unsigned char*)maskraw);
    mask_expand_kernel<<<MR/256, 256>>>(maskraw);
    // 1. layernorms
    ln_kernel<<<MR, 128>>>(a, s, lnss, p_aln, p_sln);
    // 2. P1 = sigmoid(s_ln @ ada_w_s^T + ada_b_s)
    gemm_kernel<1><<<gN8, 128>>>(p_sln, CSx, ada_ws, CSx, ada_bs, 0, 0, 0, p_P1, CAx);
    // 3. anorm = P1 * a_ln + s_ln @ ada_w_nb^T
    gemm_kernel<3><<<gN8, 128>>>(p_sln, CSx, ada_nb, CSx, 0, p_P1, p_aln, 0, p_anorm, CAx);
    // 4-7. Q,K,V,G
    gemm_kernel<0><<<gN8, 128>>>(p_anorm, CAx, wq, CAx, bq, 0, 0, 0, p_Q, CAx);
    gemm_kernel<0><<<gN8, 128>>>(p_anorm, CAx, wk, CAx, bk, 0, 0, 0, p_K, CAx);
    gemm_kernel<0><<<gN8, 128>>>(p_anorm, CAx, wv, CAx, bv, 0, 0, 0, p_V, CAx);
    gemm_kernel<1><<<gN8, 128>>>(p_anorm, CAx, wg, CAx, bg, 0, 0, 0, p_G, CAx);
    // 8. GL = sigmoid(s @ w_last^T + b_last)
    gemm_kernel<1><<<gN8, 128>>>(s, CSx, wl, CSx, bl, 0, 0, 0, p_GL, CAx);
    // 9. attention (pair bias fused from z; G-gate fused at store)
    dim3 ag(LLEN/TQ, BB);
    attn_kernel<<<ag, 128, SMEMB>>>(p_Q, p_K, p_V, p_G, z, lnz, wz, p_mf, p_O);
    // 10. out = (O @ wo^T + bo) * GL * mask
    gemm_kernel<2><<<gN8, 128>>>(p_O, CAx, wo, CAx, bo, p_GL, 0, p_mf, out, CAx);
    (void)in_sizes; (void)n_in; (void)out_size;
}

// round 6
// speedup vs baseline: 1.1655x; 1.1655x over previous
#include <cuda_runtime.h>
#include <cstdint>
#include <cstddef>

#define BB   2
#define LLEN 1024
#define CAx  512
#define CSx  384
#define CZx  64
#define HHx  16
#define DDx  32
#define MR   (BB*LLEN)
#define TQ   8
#define TK   8
#define SCALE_QK 0.17677669529663687f  // 1/sqrt(32)

typedef unsigned long long ull;
#define DINL __device__ __forceinline__

// ---------------- f32x2 packed helpers (full fp32 precision, 2x FMA rate) ----
DINL ull pk2(float x, float y){
    ull r; asm("mov.b64 %0, {%1,%2};" : "=l"(r) : "r"(__float_as_uint(x)), "r"(__float_as_uint(y)));
    return r;
}
DINL ull dup2(float x){
    unsigned u = __float_as_uint(x); ull r;
    asm("mov.b64 %0, {%1,%1};" : "=l"(r) : "r"(u));
    return r;
}
DINL float2 upk2(ull v){
    unsigned a, b; asm("mov.b64 {%0,%1}, %2;" : "=r"(a), "=r"(b) : "l"(v));
    return make_float2(__uint_as_float(a), __uint_as_float(b));
}
DINL ull ffma2(ull a, ull b, ull c){
    ull d; asm("fma.rn.f32x2 %0, %1, %2, %3;" : "=l"(d) : "l"(a), "l"(b), "l"(c));
    return d;
}
DINL ull fmul2(ull a, ull b){
    ull d; asm("mul.rn.f32x2 %0, %1, %2;" : "=l"(d) : "l"(a), "l"(b));
    return d;
}
DINL float sigf(float x){ return 1.0f / (1.0f + __expf(-x)); }

// ---------------- scratch (device globals: allocation-free) ------------------
__device__ float g_sln  [MR*CSx];
__device__ float g_aln  [MR*CAx];
__device__ float g_anorm[MR*CAx];
__device__ float g_Q    [MR*CAx];
__device__ float g_K    [MR*CAx];
__device__ float g_V    [MR*CAx];
__device__ float g_G    [MR*CAx];
__device__ float g_GL   [MR*CAx];
__device__ float g_O    [MR*CAx];
__device__ float g_maskf[MR];
__device__ int   g_masktype;

// ---------------- mask dtype sniffing + canonical decode ---------------------
__global__ void mask_detect_kernel(const unsigned char* __restrict__ m)
{
    __shared__ int s_na, s_odd0, s_f32;
    int tid = threadIdx.x;
    if (tid == 0){ s_na = 1; s_odd0 = 1; s_f32 = 1; }
    __syncthreads();
    for (int i = tid; i < 2048; i += 256){
        if ((i & 3) != 0 && m[i] != 0) atomicAnd(&s_na, 0);
    }
    const unsigned* mu = (const unsigned*)m;
    for (int i = tid; i < 512; i += 256){
        if ((i & 1) != 0 && mu[i] != 0u) atomicAnd(&s_odd0, 0);
        float f = __uint_as_float(mu[i]);
        if (!(f == 0.0f || f == 1.0f)) atomicAnd(&s_f32, 0);
    }
    __syncthreads();
    if (tid == 0){
        int t;
        if (s_na)       t = s_odd0 ? 3 : 1;   // int64 : int32
        else if (s_f32) t = 2;                // float32
        else            t = 0;                // bool/u8
        g_masktype = t;
    }
}

__global__ void mask_expand_kernel(const void* __restrict__ m)
{
    int i = blockIdx.x * 256 + threadIdx.x;
    if (i >= MR) return;
    int t = g_masktype;
    float v;
    if (t == 0)      v = ((const unsigned char*)m)[i] ? 1.f : 0.f;
    else if (t == 1) v = ((const int*)m)[i] ? 1.f : 0.f;
    else if (t == 2) v = (((const float*)m)[i] != 0.f) ? 1.f : 0.f;
    else             v = ((const long long*)m)[i] ? 1.f : 0.f;
    g_maskf[i] = v;
}

// ---------------- LayerNorm kernel: rows of a (512) and s (384) --------------
__global__ void __launch_bounds__(128) ln_kernel(
    const float* __restrict__ a, const float* __restrict__ s,
    const float* __restrict__ lnss,
    float* __restrict__ aln, float* __restrict__ sln)
{
    __shared__ float redA[8], redB[8];
    int r = blockIdx.x, tid = threadIdx.x;
    int lane = tid & 31, wid = tid >> 5;

    const float* ar = a + (size_t)r * CAx;
    float4 av = *(const float4*)(ar + tid * 4);
    float s1 = av.x + av.y + av.z + av.w;
    float s2 = av.x*av.x + av.y*av.y + av.z*av.z + av.w*av.w;
    #pragma unroll
    for (int o = 16; o > 0; o >>= 1){
        s1 += __shfl_xor_sync(~0u, s1, o);
        s2 += __shfl_xor_sync(~0u, s2, o);
    }
    if (lane == 0){ redA[wid] = s1; redA[4+wid] = s2; }

    float4 sv = make_float4(0.f,0.f,0.f,0.f);
    if (tid < 96) sv = *(const float4*)(s + (size_t)r * CSx + tid * 4);
    float t1 = sv.x + sv.y + sv.z + sv.w;
    float t2 = sv.x*sv.x + sv.y*sv.y + sv.z*sv.z + sv.w*sv.w;
    #pragma unroll
    for (int o = 16; o > 0; o >>= 1){
        t1 += __shfl_xor_sync(~0u, t1, o);
        t2 += __shfl_xor_sync(~0u, t2, o);
    }
    if (lane == 0){ redB[wid] = t1; redB[4+wid] = t2; }
    __syncthreads();

    float as1 = redA[0]+redA[1]+redA[2]+redA[3];
    float as2 = redA[4]+redA[5]+redA[6]+redA[7];
    float am = as1 * (1.f/CAx);
    float arstd = rsqrtf(as2*(1.f/CAx) - am*am + 1e-5f);
    float4 ao;
    ao.x = (av.x-am)*arstd; ao.y = (av.y-am)*arstd;
    ao.z = (av.z-am)*arstd; ao.w = (av.w-am)*arstd;
    *(float4*)(aln + (size_t)r*CAx + tid*4) = ao;

    float bs1 = redB[0]+redB[1]+redB[2]+redB[3];
    float bs2 = redB[4]+redB[5]+redB[6]+redB[7];
    float sm = bs1 * (1.f/CSx);
    float srstd = rsqrtf(bs2*(1.f/CSx) - sm*sm + 1e-5f);
    if (tid < 96){
        float4 sc = *(const float4*)(lnss + tid*4);
        float4 so;
        so.x = (sv.x-sm)*srstd*sc.x; so.y = (sv.y-sm)*srstd*sc.y;
        so.z = (sv.z-sm)*srstd*sc.z; so.w = (sv.w-sm)*srstd*sc.w;
        *(float4*)(sln + (size_t)r*CSx + tid*4) = so;
    }
}

// ---------------- generic tiled GEMM (modes 1,2) -----------------------------
// MODE 1: C = sigmoid(acc + bias)
// MODE 2: C = (acc + bias) * aux1[m,n] * maskf[m]
template<int MODE>
__global__ void __launch_bounds__(128) gemm_kernel(
    const float* __restrict__ A, int lda,
    const float* __restrict__ W, int K,
    const float* __restrict__ bias,
    const float* __restrict__ aux1,
    const float* __restrict__ maskf,
    float* __restrict__ C, int N)
{
    __shared__ float As[16][68];
    __shared__ float Bs[16][68];
    int tid = threadIdx.x;
    int tn = tid & 15, tm = tid >> 4;
    int m0 = blockIdx.y * 64, n0 = blockIdx.x * 64;

    ull acc[4][4];
    #pragma unroll
    for (int i=0;i<4;i++)
        #pragma unroll
        for (int j=0;j<4;j++) acc[i][j] = 0ull;

    for (int k0 = 0; k0 < K; k0 += 16){
        __syncthreads();
        #pragma unroll
        for (int i=0;i<2;i++){
            int u = tid + i*128;
            int m = u >> 2, kc = (u & 3) << 2;
            float4 v = *(const float4*)(A + (size_t)(m0+m)*lda + k0 + kc);
            As[kc+0][m]=v.x; As[kc+1][m]=v.y; As[kc+2][m]=v.z; As[kc+3][m]=v.w;
        }
        #pragma unroll
        for (int i=0;i<2;i++){
            int u = tid + i*128;
            int n = u >> 2, kc = (u & 3) << 2;
            float4 v = *(const float4*)(W + (size_t)(n0+n)*K + k0 + kc);
            Bs[kc+0][n]=v.x; Bs[kc+1][n]=v.y; Bs[kc+2][n]=v.z; Bs[kc+3][n]=v.w;
        }
        __syncthreads();
        #pragma unroll
        for (int kk=0; kk<16; kk++){
            ulonglong2 a01 = *(const ulonglong2*)(&As[kk][tm*8]);
            ulonglong2 a23 = *(const ulonglong2*)(&As[kk][tm*8+4]);
            float4 b4 = *(const float4*)(&Bs[kk][tn*4]);
            ull b0 = dup2(b4.x), b1 = dup2(b4.y), b2 = dup2(b4.z), b3 = dup2(b4.w);
            ull am[4] = {a01.x, a01.y, a23.x, a23.y};
            #pragma unroll
            for (int j=0;j<4;j++){
                acc[j][0] = ffma2(am[j], b0, acc[j][0]);
                acc[j][1] = ffma2(am[j], b1, acc[j][1]);
                acc[j][2] = ffma2(am[j], b2, acc[j][2]);
                acc[j][3] = ffma2(am[j], b3, acc[j][3]);
            }
        }
    }

    float4 bv = *(const float4*)(bias + n0 + tn*4);

    #pragma unroll
    for (int j=0;j<4;j++){
        int row0 = m0 + tm*8 + 2*j;
        int row1 = row0 + 1;
        float2 c0 = upk2(acc[j][0]), c1 = upk2(acc[j][1]);
        float2 c2 = upk2(acc[j][2]), c3 = upk2(acc[j][3]);
        float4 r0 = make_float4(c0.x + bv.x, c1.x + bv.y, c2.x + bv.z, c3.x + bv.w);
        float4 r1 = make_float4(c0.y + bv.x, c1.y + bv.y, c2.y + bv.z, c3.y + bv.w);
        int col = n0 + tn*4;
        if (MODE == 1){
            r0.x = sigf(r0.x); r0.y = sigf(r0.y); r0.z = sigf(r0.z); r0.w = sigf(r0.w);
            r1.x = sigf(r1.x); r1.y = sigf(r1.y); r1.z = sigf(r1.z); r1.w = sigf(r1.w);
        }
        if (MODE == 2){
            float4 g0 = *(const float4*)(aux1 + (size_t)row0*N + col);
            float4 g1 = *(const float4*)(aux1 + (size_t)row1*N + col);
            float mk0 = maskf[row0];
            float mk1 = maskf[row1];
            r0.x *= g0.x*mk0; r0.y *= g0.y*mk0; r0.z *= g0.z*mk0; r0.w *= g0.w*mk0;
            r1.x *= g1.x*mk1; r1.y *= g1.y*mk1; r1.z *= g1.z*mk1; r1.w *= g1.w*mk1;
        }
        *(float4*)(C + (size_t)row0*N + col) = r0;
        *(float4*)(C + (size_t)row1*N + col) = r1;
    }
}

// ---------------- fused ada: anorm = sig(sln@Wa^T + ba) * aln + sln@Wn^T -----
__global__ void __launch_bounds__(128) ada_kernel(
    const float* __restrict__ sln,
    const float* __restrict__ Wa, const float* __restrict__ Wn,
    const float* __restrict__ ba,
    const float* __restrict__ aln,
    float* __restrict__ anorm)
{
    __shared__ float As[16][68];
    __shared__ float B1[16][68];
    __shared__ float B2[16][68];
    int tid = threadIdx.x;
    int tn = tid & 15, tm = tid >> 4;
    int m0 = blockIdx.y * 64, n0 = blockIdx.x * 64;

    ull acc1[4][4], acc2[4][4];
    #pragma unroll
    for (int i=0;i<4;i++)
        #pragma unroll
        for (int j=0;j<4;j++){ acc1[i][j] = 0ull; acc2[i][j] = 0ull; }

    for (int k0 = 0; k0 < CSx; k0 += 16){
        __syncthreads();
        #pragma unroll
        for (int i=0;i<2;i++){
            int u = tid + i*128;
            int m = u >> 2, kc = (u & 3) << 2;
            float4 v = *(const float4*)(sln + (size_t)(m0+m)*CSx + k0 + kc);
            As[kc+0][m]=v.x; As[kc+1][m]=v.y; As[kc+2][m]=v.z; As[kc+3][m]=v.w;
        }
        #pragma unroll
        for (int i=0;i<2;i++){
            int u = tid + i*128;
            int n = u >> 2, kc = (u & 3) << 2;
            float4 v1 = *(const float4*)(Wa + (size_t)(n0+n)*CSx + k0 + kc);
            B1[kc+0][n]=v1.x; B1[kc+1][n]=v1.y; B1[kc+2][n]=v1.z; B1[kc+3][n]=v1.w;
            float4 v2 = *(const float4*)(Wn + (size_t)(n0+n)*CSx + k0 + kc);
            B2[kc+0][n]=v2.x; B2[kc+1][n]=v2.y; B2[kc+2][n]=v2.z; B2[kc+3][n]=v2.w;
        }
        __syncthreads();
        #pragma unroll
        for (int kk=0; kk<16; kk++){
            ulonglong2 a01 = *(const ulonglong2*)(&As[kk][tm*8]);
            ulonglong2 a23 = *(const ulonglong2*)(&As[kk][tm*8+4]);
            ull am[4] = {a01.x, a01.y, a23.x, a23.y};
            float4 p4 = *(const float4*)(&B1[kk][tn*4]);
            float4 q4 = *(const float4*)(&B2[kk][tn*4]);
            ull p0 = dup2(p4.x), p1 = dup2(p4.y), p2 = dup2(p4.z), p3 = dup2(p4.w);
            ull q0 = dup2(q4.x), q1 = dup2(q4.y), q2v = dup2(q4.z), q3 = dup2(q4.w);
            #pragma unroll
            for (int j=0;j<4;j++){
                acc1[j][0] = ffma2(am[j], p0, acc1[j][0]);
                acc1[j][1] = ffma2(am[j], p1, acc1[j][1]);
                acc1[j][2] = ffma2(am[j], p2, acc1[j][2]);
                acc1[j][3] = ffma2(am[j], p3, acc1[j][3]);
                acc2[j][0] = ffma2(am[j], q0, acc2[j][0]);
                acc2[j][1] = ffma2(am[j], q1, acc2[j][1]);
                acc2[j][2] = ffma2(am[j], q2v, acc2[j][2]);
                acc2[j][3] = ffma2(am[j], q3, acc2[j][3]);
            }
        }
    }

    float4 bv = *(const float4*)(ba + n0 + tn*4);
    #pragma unroll
    for (int j=0;j<4;j++){
        int row0 = m0 + tm*8 + 2*j;
        int row1 = row0 + 1;
        int col = n0 + tn*4;
        float2 s0 = upk2(acc1[j][0]), s1 = upk2(acc1[j][1]);
        float2 s2 = upk2(acc1[j][2]), s3 = upk2(acc1[j][3]);
        float2 t0 = upk2(acc2[j][0]), t1 = upk2(acc2[j][1]);
        float2 t2 = upk2(acc2[j][2]), t3 = upk2(acc2[j][3]);
        float4 a0 = *(const float4*)(aln + (size_t)row0*CAx + col);
        float4 a1 = *(const float4*)(aln + (size_t)row1*CAx + col);
        float4 r0, r1;
        r0.x = sigf(s0.x + bv.x)*a0.x + t0.x;
        r0.y = sigf(s1.x + bv.y)*a0.y + t1.x;
        r0.z = sigf(s2.x + bv.z)*a0.z + t2.x;
        r0.w = sigf(s3.x + bv.w)*a0.w + t3.x;
        r1.x = sigf(s0.y + bv.x)*a1.x + t0.y;
        r1.y = sigf(s1.y + bv.y)*a1.y + t1.y;
        r1.z = sigf(s2.y + bv.z)*a1.z + t2.y;
        r1.w = sigf(s3.y + bv.w)*a1.w + t3.y;
        *(float4*)(anorm + (size_t)row0*CAx + col) = r0;
        *(float4*)(anorm + (size_t)row1*CAx + col) = r1;
    }
}

// ---------------- combined QKVG GEMM: blockIdx.z selects weight set ----------
struct QKVGArgs {
    const float* w[4];
    const float* b[4];
    float*       o[4];
};

__global__ void __launch_bounds__(128) qkvg_kernel(
    const float* __restrict__ A, QKVGArgs args)
{
    __shared__ float As[16][68];
    __shared__ float Bs[16][68];
    int tid = threadIdx.x;
    int zi = blockIdx.z;
    const float* __restrict__ W = args.w[zi];
    const float* __restrict__ bias = args.b[zi];
    float* __restrict__ C = args.o[zi];
    int tn = tid & 15, tm = tid >> 4;
    int m0 = blockIdx.y * 64, n0 = blockIdx.x * 64;

    ull acc[4][4];
    #pragma unroll
    for (int i=0;i<4;i++)
        #pragma unroll
        for (int j=0;j<4;j++) acc[i][j] = 0ull;

    for (int k0 = 0; k0 < CAx; k0 += 16){
        __syncthreads();
        #pragma unroll
        for (int i=0;i<2;i++){
            int u = tid + i*128;
            int m = u >> 2, kc = (u & 3) << 2;
            float4 v = *(const float4*)(A + (size_t)(m0+m)*CAx + k0 + kc);
            As[kc+0][m]=v.x; As[kc+1][m]=v.y; As[kc+2][m]=v.z; As[kc+3][m]=v.w;
        }
        #pragma unroll
        for (int i=0;i<2;i++){
            int u = tid + i*128;
            int n = u >> 2, kc = (u & 3) << 2;
            float4 v = *(const float4*)(W + (size_t)(n0+n)*CAx + k0 + kc);
            Bs[kc+0][n]=v.x; Bs[kc+1][n]=v.y; Bs[kc+2][n]=v.z; Bs[kc+3][n]=v.w;
        }
        __syncthreads();
        #pragma unroll
        for (int kk=0; kk<16; kk++){
            ulonglong2 a01 = *(const ulonglong2*)(&As[kk][tm*8]);
            ulonglong2 a23 = *(const ulonglong2*)(&As[kk][tm*8+4]);
            float4 b4 = *(const float4*)(&Bs[kk][tn*4]);
            ull b0 = dup2(b4.x), b1 = dup2(b4.y), b2 = dup2(b4.z), b3 = dup2(b4.w);
            ull am[4] = {a01.x, a01.y, a23.x, a23.y};
            #pragma unroll
            for (int j=0;j<4;j++){
                acc[j][0] = ffma2(am[j], b0, acc[j][0]);
                acc[j][1] = ffma2(am[j], b1, acc[j][1]);
                acc[j][2] = ffma2(am[j], b2, acc[j][2]);
                acc[j][3] = ffma2(am[j], b3, acc[j][3]);
            }
        }
    }

    float4 bv = *(const float4*)(bias + n0 + tn*4);
    bool do_sig = (zi == 3);

    #pragma unroll
    for (int j=0;j<4;j++){
        int row0 = m0 + tm*8 + 2*j;
        int row1 = row0 + 1;
        float2 c0 = upk2(acc[j][0]), c1 = upk2(acc[j][1]);
        float2 c2 = upk2(acc[j][2]), c3 = upk2(acc[j][3]);
        float4 r0 = make_float4(c0.x + bv.x, c1.x + bv.y, c2.x + bv.z, c3.x + bv.w);
        float4 r1 = make_float4(c0.y + bv.x, c1.y + bv.y, c2.y + bv.z, c3.y + bv.w);
        if (do_sig){
            r0.x = sigf(r0.x); r0.y = sigf(r0.y); r0.z = sigf(r0.z); r0.w = sigf(r0.w);
            r1.x = sigf(r1.x); r1.y = sigf(r1.y); r1.z = sigf(r1.z); r1.w = sigf(r1.w);
        }
        int col = n0 + tn*4;
        *(float4*)(C + (size_t)row0*CAx + col) = r0;
        *(float4*)(C + (size_t)row1*CAx + col) = r1;
    }
}

// ---------------- fused flash attention with pair bias from z ----------------
#define ZS_N   (64*68)
#define KS_N   (16*260)
#define US_N   (16*68)
#define SMEMB  ((ZS_N + 2*KS_N + US_N + 16 + 64 + 64 + 8) * 4)

__global__ void __launch_bounds__(128, 3) attn_kernel(
    const float* __restrict__ Qg, const float* __restrict__ Kg,
    const float* __restrict__ Vg, const float* __restrict__ Gg,
    const float* __restrict__ z,  const float* __restrict__ lnz,
    const float* __restrict__ wz, const float* __restrict__ maskf,
    float* __restrict__ O)
{
    extern __shared__ float smf[];
    float* zs    = smf;
    float* Ks    = zs + ZS_N;
    float* Vs    = Ks + KS_N;
    float* us    = Vs + KS_N;
    float* usums = us + US_N;
    float* means = usums + 16;
    float* rstds = means + 64;
    float* maskk = rstds + 64;

    int tid = threadIdx.x;
    int h = tid & 15, qi = tid >> 4;
    int b = blockIdx.y;
    int q0 = blockIdx.x * TQ;
    int rowq = b*LLEN + q0 + qi;

    // stage u[h][c] = lnz_scale[c] * wz[h][c]
    for (int i = tid; i < 16*64; i += 128){
        int hh = i >> 6, c = i & 63;
        us[hh*68 + c] = lnz[c] * wz[hh*64 + c];
    }
    __syncthreads();
    if (tid < 16){
        float ssum = 0.f;
        #pragma unroll
        for (int c=0;c<64;c++) ssum += us[tid*68 + c];
        usums[tid] = ssum;
    }

    ull q2[16];
    {
        const float* qp = Qg + (size_t)rowq*CAx + h*DDx;
        #pragma unroll
        for (int d4=0; d4<8; d4++){
            float4 v = *(const float4*)(qp + d4*4);
            q2[2*d4]   = pk2(v.x*SCALE_QK, v.y*SCALE_QK);
            q2[2*d4+1] = pk2(v.z*SCALE_QK, v.w*SCALE_QK);
        }
    }
    float mq = maskf[rowq];

    ull o2[16];
    #pragma unroll
    for (int i=0;i<16;i++) o2[i] = 0ull;
    float mrun = -1e30f, denom = 0.f;

    for (int kt = 0; kt < LLEN/TK; kt++){
        int k0 = kt * TK;
        __syncthreads();
        // stage z tile: 8q x 8k x 64c
        #pragma unroll
        for (int i=0;i<8;i++){
            int u = tid + i*128;
            int qq = u >> 7;
            int rem = u & 127;
            int kk = rem >> 4, c4 = rem & 15;
            float4 v = *(const float4*)(z + ((size_t)((b*LLEN + q0 + qq))*LLEN + k0 + kk)*CZx + c4*4);
            *(float4*)(zs + (kk*8 + qq)*68 + c4*4) = v;
        }
        // stage K,V tiles: per-head slabs [h][k*32+d]
        #pragma unroll
        for (int i=0;i<8;i++){
            int u = tid + i*128;
            int kk = u >> 7;
            int c4 = u & 127;
            int hh = c4 >> 3, d4 = c4 & 7;
            size_t gro = ((size_t)(b*LLEN + k0 + kk))*CAx + c4*4;
            float4 kv = *(const float4*)(Kg + gro);
            *(float4*)(Ks + hh*260 + kk*32 + d4*4) = kv;
            float4 vv = *(const float4*)(Vg + gro);
            *(float4*)(Vs + hh*260 + kk*32 + d4*4) = vv;
        }
        if (tid < TK) maskk[tid] = maskf[b*LLEN + k0 + tid];
        __syncthreads();
        // LN stats for 64 (q,k) pairs, 2 threads each
        {
            int tp = tid & 1, p = tid >> 1;
            const float* zr = zs + p*68 + tp*32;
            float s1 = 0.f, s2 = 0.f;
            #pragma unroll
            for (int c=0;c<32;c+=4){
                float4 v = *(const float4*)(zr + c);
                s1 += v.x+v.y+v.z+v.w;
                s2 += v.x*v.x + v.y*v.y + v.z*v.z + v.w*v.w;
            }
            s1 += __shfl_xor_sync(~0u, s1, 1);
            s2 += __shfl_xor_sync(~0u, s2, 1);
            if (tp == 0){
                float mean = s1 * (1.f/64);
                float var  = s2 * (1.f/64) - mean*mean;
                means[p] = mean;
                rstds[p] = rsqrtf(var + 1e-5f);
            }
        }
        __syncthreads();

        // ---- phase 1: logits for all 8 keys (split accumulators, no branch div)
        float l[8];
        #pragma unroll
        for (int kk=0; kk<TK; kk++){
            if (maskk[kk] == 0.f){ l[kk] = -3.0e38f; continue; }   // uniform
            const float* zr = zs + (kk*8 + qi)*68;
            const float* ur = us + h*68;
            ull bd0 = 0ull, bd1 = 0ull;
            #pragma unroll
            for (int c4=0; c4<16; c4+=2){
                ulonglong2 z0 = *(const ulonglong2*)(zr + c4*4);
                ulonglong2 u0 = *(const ulonglong2*)(ur + c4*4);
                bd0 = ffma2(z0.x, u0.x, bd0);
                bd1 = ffma2(z0.y, u0.y, bd1);
                ulonglong2 z1 = *(const ulonglong2*)(zr + c4*4 + 4);
                ulonglong2 u1 = *(const ulonglong2*)(ur + c4*4 + 4);
                bd0 = ffma2(z1.x, u1.x, bd0);
                bd1 = ffma2(z1.y, u1.y, bd1);
            }
            float2 bf0 = upk2(bd0), bf1 = upk2(bd1);
            int p = kk*8 + qi;
            float bias = rstds[p] * ((bf0.x + bf0.y + bf1.x + bf1.y) - means[p]*usums[h]);

            const float* kr = Ks + h*260 + kk*32;
            ull qa0 = 0ull, qa1 = 0ull;
            #pragma unroll
            for (int d4=0; d4<8; d4++){
                ulonglong2 kk2 = *(const ulonglong2*)(kr + d4*4);
                qa0 = ffma2(kk2.x, q2[2*d4],   qa0);
                qa1 = ffma2(kk2.y, q2[2*d4+1], qa1);
            }
            float2 qf0 = upk2(qa0), qf1 = upk2(qa1);
            l[kk] = qf0.x + qf0.y + qf1.x + qf1.y + bias;
        }

        // ---- phase 2: one rescale per tile, then accumulate unmasked keys
        float lt = l[0];
        #pragma unroll
        for (int kk=1; kk<TK; kk++) lt = fmaxf(lt, l[kk]);
        float mnew = fmaxf(mrun, lt);
        float corr = __expf(mrun - mnew);
        mrun = mnew;
        denom *= corr;
        ull c2 = dup2(corr);
        #pragma unroll
        for (int i=0;i<16;i++) o2[i] = fmul2(o2[i], c2);

        #pragma unroll
        for (int kk=0; kk<TK; kk++){
            if (maskk[kk] == 0.f) continue;   // uniform
            float pe = __expf(l[kk] - mnew);
            denom += pe;
            ull p2v = dup2(pe);
            const float* vr = Vs + h*260 + kk*32;
            #pragma unroll
            for (int d4=0; d4<8; d4++){
                ulonglong2 vv = *(const ulonglong2*)(vr + d4*4);
                o2[2*d4]   = ffma2(vv.x, p2v, o2[2*d4]);
                o2[2*d4+1] = ffma2(vv.y, p2v, o2[2*d4+1]);
            }
        }
    }

    float inv = (denom > 0.f) ? (mq / denom) : 0.f;
    ull inv2 = dup2(inv);
    const float* gp = Gg + (size_t)rowq*CAx + h*DDx;
    float* op = O + (size_t)rowq*CAx + h*DDx;
    #pragma unroll
    for (int d4=0; d4<8; d4++){
        float4 g4 = *(const float4*)(gp + d4*4);
        float2 aa = upk2(fmul2(o2[2*d4],   inv2));
        float2 bb = upk2(fmul2(o2[2*d4+1], inv2));
        float4 r = make_float4(aa.x*g4.x, aa.y*g4.y, bb.x*g4.z, bb.y*g4.w);
        *(float4*)(op + d4*4) = r;
    }
}

// ---------------- launch ----------------------------------------------------
extern "C" void kernel_launch(void* const* d_in, const int* in_sizes, int n_in,
                              void* d_out, int out_size)
{
    const float* a      = (const float*)d_in[0];
    const float* s      = (const float*)d_in[1];
    const float* z      = (const float*)d_in[2];
    const float* lnss   = (const float*)d_in[3];
    const float* ada_ws = (const float*)d_in[4];
    const float* ada_bs = (const float*)d_in[5];
    const float* ada_nb = (const float*)d_in[6];
    const float* wq     = (const float*)d_in[7];
    const float* bq     = (const float*)d_in[8];
    const float* wk     = (const float*)d_in[9];
    const float* bk     = (const float*)d_in[10];
    const float* wv     = (const float*)d_in[11];
    const float* bv     = (const float*)d_in[12];
    const float* wg     = (const float*)d_in[13];
    const float* bg     = (const float*)d_in[14];
    const float* wo     = (const float*)d_in[15];
    const float* bo     = (const float*)d_in[16];
    const float* lnz    = (const float*)d_in[17];
    const float* wz     = (const float*)d_in[18];
    const float* wl     = (const float*)d_in[19];
    const float* bl     = (const float*)d_in[20];
    const void*  maskraw= d_in[21];
    float* out = (float*)d_out;

    float *p_sln, *p_aln, *p_anorm, *p_Q, *p_K, *p_V, *p_G, *p_GL, *p_O, *p_mf;
    cudaGetSymbolAddress((void**)&p_sln,   g_sln);
    cudaGetSymbolAddress((void**)&p_aln,   g_aln);
    cudaGetSymbolAddress((void**)&p_anorm, g_anorm);
    cudaGetSymbolAddress((void**)&p_Q,     g_Q);
    cudaGetSymbolAddress((void**)&p_K,     g_K);
    cudaGetSymbolAddress((void**)&p_V,     g_V);
    cudaGetSymbolAddress((void**)&p_G,     g_G);
    cudaGetSymbolAddress((void**)&p_GL,    g_GL);
    cudaGetSymbolAddress((void**)&p_O,     g_O);
    cudaGetSymbolAddress((void**)&p_mf,    g_maskf);

    cudaFuncSetAttribute(attn_kernel, cudaFuncAttributeMaxDynamicSharedMemorySize, SMEMB);

    dim3 gN8(CAx/64, MR/64);       // (8, 32)
    dim3 g4(CAx/64, MR/64, 4);     // combined QKVG

    // 0. canonicalize mask -> float[MR]
    mask_detect_kernel<<<1, 256>>>((const unsigned char*)maskraw);
    mask_expand_kernel<<<MR/256, 256>>>(maskraw);
    // 1. layernorms
    ln_kernel<<<MR, 128>>>(a, s, lnss, p_aln, p_sln);
    // 2. fused ada: anorm = sig(sln@Wa^T + ba)*aln + sln@Wn^T
    ada_kernel<<<gN8, 128>>>(p_sln, ada_ws, ada_nb, ada_bs, p_aln, p_anorm);
    // 3. Q,K,V,G combined
    QKVGArgs qa;
    qa.w[0]=wq; qa.w[1]=wk; qa.w[2]=wv; qa.w[3]=wg;
    qa.b[0]=bq; qa.b[1]=bk; qa.b[2]=bv; qa.b[3]=bg;
    qa.o[0]=p_Q; qa.o[1]=p_K; qa.o[2]=p_V; qa.o[3]=p_G;
    qkvg_kernel<<<g4, 128>>>(p_anorm, qa);
    // 4. GL = sigmoid(s @ w_last^T + b_last)
    gemm_kernel<1><<<gN8, 128>>>(s, CSx, wl, CSx, bl, 0, 0, p_GL, CAx);
    // 5. attention (pair bias fused from z; G-gate fused at store)
    dim3 ag(LLEN/TQ, BB);
    attn_kernel<<<ag, 128, SMEMB>>>(p_Q, p_K, p_V, p_G, z, lnz, wz, p_mf, p_O);
    // 6. out = (O @ wo^T + bo) * GL * mask
    gemm_kernel<2><<<gN8, 128>>>(p_O, CAx, wo, CAx, bo, p_GL, p_mf, out, CAx);
    (void)in_sizes; (void)n_in; (void)out_size;
}